// round 3
// baseline (speedup 1.0000x reference)
#include <cuda_runtime.h>
#include <cuda_bf16.h>
#include <math.h>
#include <stdint.h>

// Problem constants (fixed by the reference)
#define BB 2048
#define EE 512
#define CC 16384
// TEMPERATURE=0.05 -> 1/T = 20; TAU=4 -> scale/TAU: same=0.25, diff=0.125
// ramp = (epoch/150) * 1.0 * 16

// ---------------- device scratch (no allocations allowed) ----------------
__device__ __nv_bfloat16 g_bat[BB * EE];          // 2 MB
__device__ __nv_bfloat16 g_tea[BB * EE];          // 2 MB
__device__ __nv_bfloat16 g_cmn[CC * EE];          // 16 MB  (normalized class_map, bf16)
__device__ float         g_logits[(size_t)BB * CC]; // 128 MB
__device__ float         g_sim[(size_t)BB * BB];    // 16 MB
__device__ float         g_tsim[(size_t)BB * BB];   // 16 MB
__device__ float         g_inv[CC];               // 1/||class_map_row||
__device__ float         g_lablogit[BB];          // fp32 exact label logits
__device__ float         g_rowv[BB];              // per-row (lse - label_logit)
__device__ float         g_kl[BB];                // per-row KL
__device__ int           g_lab32[BB];             // decoded labels

// ---------------- helpers ----------------
__device__ __forceinline__ void mma16816(float* c, const uint32_t* a, const uint32_t* b) {
    asm volatile(
        "mma.sync.aligned.m16n8k16.row.col.f32.bf16.bf16.f32 "
        "{%0,%1,%2,%3}, {%4,%5,%6,%7}, {%8,%9}, {%0,%1,%2,%3};\n"
        : "+f"(c[0]), "+f"(c[1]), "+f"(c[2]), "+f"(c[3])
        : "r"(a[0]), "r"(a[1]), "r"(a[2]), "r"(a[3]), "r"(b[0]), "r"(b[1]));
}

__device__ __forceinline__ void ldsm4(uint32_t* r, uint32_t saddr) {
    asm volatile("ldmatrix.sync.aligned.m8n8.x4.shared.b16 {%0,%1,%2,%3}, [%4];\n"
                 : "=r"(r[0]), "=r"(r[1]), "=r"(r[2]), "=r"(r[3]) : "r"(saddr));
}

// ---------------- label decode (int32 vs int64 robust) ----------------
__global__ void k_labels(const int* __restrict__ raw) {
    __shared__ int is64;
    if (threadIdx.x == 0) {
        int ok = 1;
        for (int i = 0; i < 64; i++)
            if (raw[2 * i + 1] != 0) { ok = 0; break; }
        is64 = ok;  // random int32 labels have ~0 chance of 64 zero odd-slots
    }
    __syncthreads();
    int f = is64;
    for (int i = threadIdx.x; i < BB; i += blockDim.x)
        g_lab32[i] = f ? raw[2 * i] : raw[i];
}

// ---------------- class_map: row norm + normalized bf16 convert ----------------
__global__ void k_prep_cm(const float* __restrict__ cmap) {
    int c = blockIdx.x;                        // one block (128 thr) per row
    int t = threadIdx.x;
    const float4* row = (const float4*)(cmap + (size_t)c * EE);
    float4 v = row[t];                          // cols [4t, 4t+3]
    float ss = v.x * v.x + v.y * v.y + v.z * v.z + v.w * v.w;
    #pragma unroll
    for (int o = 16; o; o >>= 1) ss += __shfl_xor_sync(0xffffffffu, ss, o);
    __shared__ float sred[4];
    if ((t & 31) == 0) sred[t >> 5] = ss;
    __syncthreads();
    float tot = sred[0] + sred[1] + sred[2] + sred[3];
    float inv = 1.0f / sqrtf(tot);
    if (t == 0) g_inv[c] = inv;
    __nv_bfloat162* drow = (__nv_bfloat162*)(g_cmn + (size_t)c * EE);
    drow[t * 2 + 0] = __floats2bfloat162_rn(v.x * inv, v.y * inv);
    drow[t * 2 + 1] = __floats2bfloat162_rn(v.z * inv, v.w * inv);
}

// ---------------- batch/teacher -> bf16 ----------------
__global__ void k_prep_vec(const float* __restrict__ batch, const float* __restrict__ teacher) {
    const int n = BB * EE / 4;
    for (int i = blockIdx.x * blockDim.x + threadIdx.x; i < n; i += gridDim.x * blockDim.x) {
        float4 b = ((const float4*)batch)[i];
        ((__nv_bfloat162*)g_bat)[i * 2 + 0] = __floats2bfloat162_rn(b.x, b.y);
        ((__nv_bfloat162*)g_bat)[i * 2 + 1] = __floats2bfloat162_rn(b.z, b.w);
        float4 s = ((const float4*)teacher)[i];
        ((__nv_bfloat162*)g_tea)[i * 2 + 0] = __floats2bfloat162_rn(s.x, s.y);
        ((__nv_bfloat162*)g_tea)[i * 2 + 1] = __floats2bfloat162_rn(s.z, s.w);
    }
}

// ---------------- exact fp32 label logit per row (one warp per row) ----------------
__global__ void k_lab(const float* __restrict__ batch, const float* __restrict__ cmap) {
    int gw = (blockIdx.x * blockDim.x + threadIdx.x) >> 5;
    int lane = threadIdx.x & 31;
    if (gw >= BB) return;
    int l = g_lab32[gw];
    const float* br = batch + (size_t)gw * EE;
    const float* cr = cmap + (size_t)l * EE;
    float s = 0.f;
    #pragma unroll 4
    for (int i = lane; i < EE; i += 32) s = fmaf(br[i], cr[i], s);
    #pragma unroll
    for (int o = 16; o; o >>= 1) s += __shfl_xor_sync(0xffffffffu, s, o);
    if (lane == 0) g_lablogit[gw] = s * g_inv[l] * 20.0f;
}

// ---------------- generic bf16 GEMM: C[M,N] = X[M,K] * Y[N,K]^T * scale ----------------
// MODE 0: logits = bat * cmn^T * 20   (N=16384, ldc=16384)
// MODE 1: sim    = bat * bat^T        (N=2048)
// MODE 2: tsim   = tea * tea^T        (N=2048)
template <int MODE>
__global__ void __launch_bounds__(256) k_gemm() {
    const __nv_bfloat16 *X, *Y;
    float* Cg; int ldc; float scale;
    if constexpr (MODE == 0) { X = g_bat; Y = g_cmn; Cg = g_logits; ldc = CC; scale = 20.0f; }
    else if constexpr (MODE == 1) { X = g_bat; Y = g_bat; Cg = g_sim; ldc = BB; scale = 1.0f; }
    else { X = g_tea; Y = g_tea; Cg = g_tsim; ldc = BB; scale = 1.0f; }

    // 128x128 tile, BK=32, padded rows (stride 40 bf16 = 80B -> ldmatrix conflict-free)
    __shared__ __nv_bfloat16 As[128 * 40];
    __shared__ __nv_bfloat16 Bs[128 * 40];

    const int tid = threadIdx.x, lane = tid & 31, wid = tid >> 5;
    const int wm = (wid >> 2) * 64, wn = (wid & 3) * 32;    // warp grid 2(m) x 4(n)
    const int bm = blockIdx.x * 128, bn = blockIdx.y * 128;

    float acc[4][4][4];
    #pragma unroll
    for (int i = 0; i < 4; i++)
        #pragma unroll
        for (int j = 0; j < 4; j++)
            #pragma unroll
            for (int k = 0; k < 4; k++) acc[i][j][k] = 0.f;

    const uint32_t aBase = (uint32_t)__cvta_generic_to_shared(As);
    const uint32_t bBase = (uint32_t)__cvta_generic_to_shared(Bs);

    // precompute ldmatrix lane addresses (element offsets)
    const int aRow = (lane & 15), aCol = (lane >> 4) * 8;
    const int gq = lane >> 3;
    const int bRowBase = ((gq >> 1) << 3) + (lane & 7);
    const int bCol = (gq & 1) << 3;

    for (int kt = 0; kt < EE; kt += 32) {
        #pragma unroll
        for (int i = 0; i < 2; i++) {
            int idx = tid + i * 256;
            int r = idx >> 2, ch = idx & 3;
            *(uint4*)(As + r * 40 + ch * 8) = *(const uint4*)(X + (size_t)(bm + r) * EE + kt + ch * 8);
            *(uint4*)(Bs + r * 40 + ch * 8) = *(const uint4*)(Y + (size_t)(bn + r) * EE + kt + ch * 8);
        }
        __syncthreads();
        #pragma unroll
        for (int ks = 0; ks < 2; ks++) {
            const int kk = ks * 16;
            uint32_t af[4][4], bf[4][2];
            #pragma unroll
            for (int im = 0; im < 4; im++) {
                int row = wm + im * 16 + aRow;
                ldsm4(af[im], aBase + (uint32_t)(row * 40 + kk + aCol) * 2);
            }
            #pragma unroll
            for (int np = 0; np < 2; np++) {
                int nloc = wn + np * 16 + bRowBase;
                uint32_t rr[4];
                ldsm4(rr, bBase + (uint32_t)(nloc * 40 + kk + bCol) * 2);
                bf[np * 2 + 0][0] = rr[0]; bf[np * 2 + 0][1] = rr[1];
                bf[np * 2 + 1][0] = rr[2]; bf[np * 2 + 1][1] = rr[3];
            }
            #pragma unroll
            for (int im = 0; im < 4; im++)
                #pragma unroll
                for (int in = 0; in < 4; in++)
                    mma16816(acc[im][in], af[im], bf[in]);
        }
        __syncthreads();
    }

    #pragma unroll
    for (int im = 0; im < 4; im++) {
        int r0 = bm + wm + im * 16 + (lane >> 2);
        #pragma unroll
        for (int in = 0; in < 4; in++) {
            int c0 = bn + wn + in * 8 + (lane & 3) * 2;
            float2 v0 = make_float2(acc[im][in][0] * scale, acc[im][in][1] * scale);
            float2 v1 = make_float2(acc[im][in][2] * scale, acc[im][in][3] * scale);
            *(float2*)(Cg + (size_t)r0 * ldc + c0) = v0;
            *(float2*)(Cg + (size_t)(r0 + 8) * ldc + c0) = v1;
        }
    }
}

// ---------------- per-row logsumexp over logits + label term ----------------
__global__ void k_rank() {
    int b = blockIdx.x, t = threadIdx.x;
    const float* row = g_logits + (size_t)b * CC;
    float M = -1e30f, S = 0.f;
    for (int j = t; j < CC; j += 256) {
        float x = row[j];
        if (x <= M) S += expf(x - M);
        else { S = S * expf(M - x) + 1.f; M = x; }
    }
    __shared__ float sM[256], sS[256];
    sM[t] = M; sS[t] = S;
    __syncthreads();
    for (int s = 128; s > 0; s >>= 1) {
        if (t < s) {
            float m2 = sM[t + s], s2 = sS[t + s];
            float Mn = fmaxf(sM[t], m2);
            sS[t] = sS[t] * expf(sM[t] - Mn) + s2 * expf(m2 - Mn);
            sM[t] = Mn;
        }
        __syncthreads();
    }
    if (t == 0) g_rowv[b] = sM[0] + logf(sS[0]) - g_lablogit[b];
}

// ---------------- per-row KD KL ----------------
__global__ void k_kd() {
    int b = blockIdx.x, t = threadIdx.x;
    int labb = g_lab32[b];
    const float* sr = g_sim  + (size_t)b * BB;
    const float* tr = g_tsim + (size_t)b * BB;
    float Mx = -1e30f, Sx = 0.f, My = -1e30f, Sy = 0.f, U = 0.f;
    for (int j = t; j < BB; j += 256) {
        float sc = (g_lab32[j] == labb) ? 0.25f : 0.125f;  // scale/TAU
        float x = sr[j] * sc, y = tr[j] * sc;
        if (x <= Mx) Sx += expf(x - Mx);
        else { Sx = Sx * expf(Mx - x) + 1.f; Mx = x; }
        float d = y - x;
        if (y <= My) { float e = expf(y - My); Sy += e; U += e * d; }
        else { float r = expf(My - y); Sy = Sy * r + 1.f; U = U * r + d; My = y; }
    }
    __shared__ float sMx[256], sSx[256], sMy[256], sSy[256], sU[256];
    sMx[t] = Mx; sSx[t] = Sx; sMy[t] = My; sSy[t] = Sy; sU[t] = U;
    __syncthreads();
    for (int s = 128; s > 0; s >>= 1) {
        if (t < s) {
            // (Mx,Sx)
            float m2 = sMx[t + s], s2 = sSx[t + s];
            float Mn = fmaxf(sMx[t], m2);
            sSx[t] = sSx[t] * expf(sMx[t] - Mn) + s2 * expf(m2 - Mn);
            sMx[t] = Mn;
            // (My,Sy,U)
            float my2 = sMy[t + s], sy2 = sSy[t + s], u2 = sU[t + s];
            float Myn = fmaxf(sMy[t], my2);
            float r1 = expf(sMy[t] - Myn), r2 = expf(my2 - Myn);
            sSy[t] = sSy[t] * r1 + sy2 * r2;
            sU[t]  = sU[t]  * r1 + u2  * r2;
            sMy[t] = Myn;
        }
        __syncthreads();
    }
    if (t == 0) {
        float lsex = sMx[0] + logf(sSx[0]);
        float lsey = sMy[0] + logf(sSy[0]);
        g_kl[b] = sU[0] / sSy[0] + lsex - lsey;   // sum p_t * (t_logp - s_logp)
    }
}

// ---------------- final deterministic reduction ----------------
__global__ void k_final(const int* __restrict__ epoch_raw, int have_epoch,
                        float* __restrict__ out, int out_size) {
    int t = threadIdx.x;
    float a = 0.f, b = 0.f;
    for (int i = t; i < BB; i += 256) { a += g_rowv[i]; b += g_kl[i]; }
    __shared__ float sa[256], sb[256];
    sa[t] = a; sb[t] = b;
    __syncthreads();
    for (int s = 128; s > 0; s >>= 1) {
        if (t < s) { sa[t] += sa[t + s]; sb[t] += sb[t + s]; }
        __syncthreads();
    }
    if (t == 0) {
        float ep = 75.0f;
        if (have_epoch) {
            int iv = epoch_raw[0];
            if (iv >= 0 && iv <= 1000000) ep = (float)iv;       // int32/int64 LE
            else ep = __int_as_float(iv);                        // float32 fallback
        }
        float loss_rank = sa[0] * (1.0f / BB);
        float loss_kd   = sb[0] * (1.0f / BB);
        float ramp = (ep / 150.0f) * 16.0f;                      // ALPHA*TAU^2
        float loss = loss_rank + ramp * loss_kd;
        out[0] = loss;
        if (out_size > 1) out[1] = loss_rank;
        if (out_size > 2) out[2] = loss_kd;
    }
}

// ---------------- launch ----------------
extern "C" void kernel_launch(void* const* d_in, const int* in_sizes, int n_in,
                              void* d_out, int out_size) {
    const float* batch   = (const float*)d_in[0];
    const float* teacher = (const float*)d_in[1];
    const float* cmap    = (const float*)d_in[2];
    const int*   labraw  = (const int*)d_in[3];
    const int*   epochp  = (n_in >= 5) ? (const int*)d_in[4] : (const int*)d_in[3];
    int have_epoch = (n_in >= 5) ? 1 : 0;
    float* out = (float*)d_out;

    k_labels<<<1, 256>>>(labraw);
    k_prep_cm<<<CC, 128>>>(cmap);
    k_prep_vec<<<512, 256>>>(batch, teacher);
    k_lab<<<BB / 8, 256>>>(batch, cmap);            // 8 warps/block, one warp per row

    dim3 gL(BB / 128, CC / 128);                    // 16 x 128
    k_gemm<0><<<gL, 256>>>();
    dim3 gS(BB / 128, BB / 128);                    // 16 x 16
    k_gemm<1><<<gS, 256>>>();
    k_gemm<2><<<gS, 256>>>();

    k_rank<<<BB, 256>>>();
    k_kd<<<BB, 256>>>();
    k_final<<<1, 256>>>(epochp, have_epoch, out, out_size);
}

// round 6
// speedup vs baseline: 1.3406x; 1.3406x over previous
#include <cuda_runtime.h>
#include <cuda_bf16.h>
#include <math.h>
#include <stdint.h>

// Problem constants (fixed by the reference)
#define BB 2048
#define EE 512
#define CC 16384
// TEMPERATURE=0.05 -> 1/T = 20; TAU=4 -> scale/TAU: same=0.25, diff=0.125
// ramp = (epoch/150) * 1.0 * 16

// ---------------- device scratch (no allocations allowed) ----------------
__device__ __nv_bfloat16 g_bat[BB * EE];            // 2 MB
__device__ __nv_bfloat16 g_tea[BB * EE];            // 2 MB
__device__ __nv_bfloat16 g_cmn[CC * EE];            // 16 MB (normalized class_map bf16)
__device__ float         g_sim[(size_t)BB * BB];    // 16 MB
__device__ float         g_tsim[(size_t)BB * BB];   // 16 MB
__device__ float         g_pm[(size_t)BB * 128];    // 1 MB  per-(row, Ntile) max
__device__ float         g_ps[(size_t)BB * 128];    // 1 MB  per-(row, Ntile) sumexp
__device__ float         g_inv[CC];                 // 1/||class_map_row||
__device__ float         g_lablogit[BB];            // fp32 exact label logits
__device__ float         g_rowv[BB];                // per-row (lse - label_logit)
__device__ float         g_kl[BB];                  // per-row KL
__device__ int           g_lab32[BB];               // decoded labels

// ---------------- helpers ----------------
__device__ __forceinline__ void mma16816(float* c, const uint32_t* a, const uint32_t* b) {
    asm volatile(
        "mma.sync.aligned.m16n8k16.row.col.f32.bf16.bf16.f32 "
        "{%0,%1,%2,%3}, {%4,%5,%6,%7}, {%8,%9}, {%0,%1,%2,%3};\n"
        : "+f"(c[0]), "+f"(c[1]), "+f"(c[2]), "+f"(c[3])
        : "r"(a[0]), "r"(a[1]), "r"(a[2]), "r"(a[3]), "r"(b[0]), "r"(b[1]));
}

__device__ __forceinline__ void ldsm4(uint32_t* r, uint32_t saddr) {
    asm volatile("ldmatrix.sync.aligned.m8n8.x4.shared.b16 {%0,%1,%2,%3}, [%4];\n"
                 : "=r"(r[0]), "=r"(r[1]), "=r"(r[2]), "=r"(r[3]) : "r"(saddr));
}

__device__ __forceinline__ void cp16(uint32_t saddr, const void* gptr) {
    asm volatile("cp.async.cg.shared.global [%0], [%1], 16;\n" :: "r"(saddr), "l"(gptr));
}

// ---------------- label decode (int32 vs int64 robust) ----------------
__global__ void k_labels(const int* __restrict__ raw) {
    __shared__ int is64;
    if (threadIdx.x == 0) {
        int ok = 1;
        for (int i = 0; i < 64; i++)
            if (raw[2 * i + 1] != 0) { ok = 0; break; }
        is64 = ok;  // random int32 labels have ~0 chance of 64 zero odd-slots
    }
    __syncthreads();
    int f = is64;
    for (int i = threadIdx.x; i < BB; i += blockDim.x)
        g_lab32[i] = f ? raw[2 * i] : raw[i];
}

// ---------------- class_map: row norm + normalized bf16 convert ----------------
__global__ void k_prep_cm(const float* __restrict__ cmap) {
    int c = blockIdx.x;                        // one block (128 thr) per row
    int t = threadIdx.x;
    const float4* row = (const float4*)(cmap + (size_t)c * EE);
    float4 v = row[t];                          // cols [4t, 4t+3]
    float ss = v.x * v.x + v.y * v.y + v.z * v.z + v.w * v.w;
    #pragma unroll
    for (int o = 16; o; o >>= 1) ss += __shfl_xor_sync(0xffffffffu, ss, o);
    __shared__ float sred[4];
    if ((t & 31) == 0) sred[t >> 5] = ss;
    __syncthreads();
    float tot = sred[0] + sred[1] + sred[2] + sred[3];
    float inv = 1.0f / sqrtf(tot);
    if (t == 0) g_inv[c] = inv;
    __nv_bfloat162* drow = (__nv_bfloat162*)(g_cmn + (size_t)c * EE);
    drow[t * 2 + 0] = __floats2bfloat162_rn(v.x * inv, v.y * inv);
    drow[t * 2 + 1] = __floats2bfloat162_rn(v.z * inv, v.w * inv);
}

// ---------------- batch/teacher -> bf16 ----------------
__global__ void k_prep_vec(const float* __restrict__ batch, const float* __restrict__ teacher) {
    const int n = BB * EE / 4;
    for (int i = blockIdx.x * blockDim.x + threadIdx.x; i < n; i += gridDim.x * blockDim.x) {
        float4 b = ((const float4*)batch)[i];
        ((__nv_bfloat162*)g_bat)[i * 2 + 0] = __floats2bfloat162_rn(b.x, b.y);
        ((__nv_bfloat162*)g_bat)[i * 2 + 1] = __floats2bfloat162_rn(b.z, b.w);
        float4 s = ((const float4*)teacher)[i];
        ((__nv_bfloat162*)g_tea)[i * 2 + 0] = __floats2bfloat162_rn(s.x, s.y);
        ((__nv_bfloat162*)g_tea)[i * 2 + 1] = __floats2bfloat162_rn(s.z, s.w);
    }
}

// ---------------- exact fp32 label logit per row (one warp per row) ----------------
__global__ void k_lab(const float* __restrict__ batch, const float* __restrict__ cmap) {
    int gw = (blockIdx.x * blockDim.x + threadIdx.x) >> 5;
    int lane = threadIdx.x & 31;
    if (gw >= BB) return;
    int l = g_lab32[gw];
    const float4* br = (const float4*)(batch + (size_t)gw * EE);
    const float4* cr = (const float4*)(cmap + (size_t)l * EE);
    float s = 0.f;
    #pragma unroll
    for (int i = 0; i < 4; i++) {
        float4 b = br[lane + i * 32];
        float4 c = cr[lane + i * 32];
        s = fmaf(b.x, c.x, s); s = fmaf(b.y, c.y, s);
        s = fmaf(b.z, c.z, s); s = fmaf(b.w, c.w, s);
    }
    #pragma unroll
    for (int o = 16; o; o >>= 1) s += __shfl_xor_sync(0xffffffffu, s, o);
    if (lane == 0) g_lablogit[gw] = s * g_inv[l] * 20.0f;
}

// ---------------- generic bf16 GEMM: C[M,N] = X[M,K] * Y[N,K]^T ----------------
// MODE 0: logits GEMM, fused per-row (max, sumexp) partials (scale 20)
// MODE 1: sim  = bat * bat^T -> g_sim
// MODE 2: tsim = tea * tea^T -> g_tsim
// 128x128 tile, BK=32, 2-stage cp.async pipeline, padded smem rows (40 bf16).
template <int MODE>
__global__ void __launch_bounds__(256) k_gemm() {
    const __nv_bfloat16 *X, *Y;
    float* Cg = nullptr; int ldc = 0;
    if constexpr (MODE == 0) { X = g_bat; Y = g_cmn; }
    else if constexpr (MODE == 1) { X = g_bat; Y = g_bat; Cg = g_sim; ldc = BB; }
    else { X = g_tea; Y = g_tea; Cg = g_tsim; ldc = BB; }

    __shared__ __nv_bfloat16 As[2][128 * 40];
    __shared__ __nv_bfloat16 Bs[2][128 * 40];

    const int tid = threadIdx.x, lane = tid & 31, wid = tid >> 5;
    const int wm = (wid >> 2) * 64, wn = (wid & 3) * 32;    // warp grid 2(m) x 4(n)
    const int bm = blockIdx.x * 128, bn = blockIdx.y * 128;

    float acc[4][4][4];
    #pragma unroll
    for (int i = 0; i < 4; i++)
        #pragma unroll
        for (int j = 0; j < 4; j++)
            #pragma unroll
            for (int k = 0; k < 4; k++) acc[i][j][k] = 0.f;

    const uint32_t aB0 = (uint32_t)__cvta_generic_to_shared(&As[0][0]);
    const uint32_t aB1 = (uint32_t)__cvta_generic_to_shared(&As[1][0]);
    const uint32_t bB0 = (uint32_t)__cvta_generic_to_shared(&Bs[0][0]);
    const uint32_t bB1 = (uint32_t)__cvta_generic_to_shared(&Bs[1][0]);

    // loader: each thread does 2 x 16B for A and 2 x 16B for B
    const int lr = tid >> 2, lch = tid & 3;
    const uint32_t loff0 = (uint32_t)(lr * 40 + lch * 8) * 2;
    const uint32_t loff1 = (uint32_t)((lr + 64) * 40 + lch * 8) * 2;

    auto load_tile = [&](int kt, int buf) {
        uint32_t ab = buf ? aB1 : aB0;
        uint32_t bb = buf ? bB1 : bB0;
        const __nv_bfloat16* xs = X + (size_t)(bm + lr) * EE + kt + lch * 8;
        const __nv_bfloat16* ys = Y + (size_t)(bn + lr) * EE + kt + lch * 8;
        cp16(ab + loff0, xs);
        cp16(ab + loff1, xs + (size_t)64 * EE);
        cp16(bb + loff0, ys);
        cp16(bb + loff1, ys + (size_t)64 * EE);
        asm volatile("cp.async.commit_group;\n");
    };

    // ldmatrix lane address components
    const int aRow = (lane & 15), aCol = (lane >> 4) * 8;
    const int gq = lane >> 3;
    const int bRowBase = ((gq >> 1) << 3) + (lane & 7);
    const int bCol = (gq & 1) << 3;

    load_tile(0, 0);

    const int NT = EE / 32;   // 16
    for (int t = 0; t < NT; t++) {
        if (t + 1 < NT) {
            load_tile((t + 1) * 32, (t + 1) & 1);
            asm volatile("cp.async.wait_group %0;\n" :: "n"(1));
        } else {
            asm volatile("cp.async.wait_group %0;\n" :: "n"(0));
        }
        __syncthreads();
        uint32_t aBase = (t & 1) ? aB1 : aB0;
        uint32_t bBase = (t & 1) ? bB1 : bB0;
        #pragma unroll
        for (int ks = 0; ks < 2; ks++) {
            const int kk = ks * 16;
            uint32_t af[4][4], bf[4][2];
            #pragma unroll
            for (int im = 0; im < 4; im++) {
                int row = wm + im * 16 + aRow;
                ldsm4(af[im], aBase + (uint32_t)(row * 40 + kk + aCol) * 2);
            }
            #pragma unroll
            for (int np = 0; np < 2; np++) {
                int nloc = wn + np * 16 + bRowBase;
                uint32_t rr[4];
                ldsm4(rr, bBase + (uint32_t)(nloc * 40 + kk + bCol) * 2);
                bf[np * 2 + 0][0] = rr[0]; bf[np * 2 + 0][1] = rr[1];
                bf[np * 2 + 1][0] = rr[2]; bf[np * 2 + 1][1] = rr[3];
            }
            #pragma unroll
            for (int im = 0; im < 4; im++)
                #pragma unroll
                for (int in = 0; in < 4; in++)
                    mma16816(acc[im][in], af[im], bf[in]);
        }
        __syncthreads();
    }

    if constexpr (MODE == 0) {
        // Fused epilogue: per-row (max, sumexp) of 20*acc over this block's 128 cols.
        // Thread holds 8 rows x 8 cols; quad (lane&3) spans cols.
        float2* red = (float2*)&As[0][0];       // [128][4], 4 KB
        const int qrow = lane >> 2, qcol = lane & 3;
        #pragma unroll
        for (int im = 0; im < 4; im++) {
            #pragma unroll
            for (int h = 0; h < 2; h++) {
                float m = -1e30f;
                #pragma unroll
                for (int in = 0; in < 4; in++)
                    m = fmaxf(m, fmaxf(acc[im][in][2 * h], acc[im][in][2 * h + 1]));
                m = fmaxf(m, __shfl_xor_sync(0xffffffffu, m, 1));
                m = fmaxf(m, __shfl_xor_sync(0xffffffffu, m, 2));
                float s = 0.f;
                #pragma unroll
                for (int in = 0; in < 4; in++) {
                    s += expf((acc[im][in][2 * h]     - m) * 20.0f);
                    s += expf((acc[im][in][2 * h + 1] - m) * 20.0f);
                }
                s += __shfl_xor_sync(0xffffffffu, s, 1);
                s += __shfl_xor_sync(0xffffffffu, s, 2);
                if (qcol == 0) {
                    int rloc = wm + im * 16 + qrow + 8 * h;
                    red[rloc * 4 + (wid & 3)] = make_float2(m * 20.0f, s);
                }
            }
        }
        __syncthreads();
        if (tid < 128) {
            float M = -1e30f, S = 0.f;
            #pragma unroll
            for (int w = 0; w < 4; w++) {
                float2 p = red[tid * 4 + w];
                float Mn = fmaxf(M, p.x);
                S = S * expf(M - Mn) + p.y * expf(p.x - Mn);
                M = Mn;
            }
            size_t o = (size_t)(bm + tid) * 128 + blockIdx.y;
            g_pm[o] = M;
            g_ps[o] = S;
        }
    } else {
        #pragma unroll
        for (int im = 0; im < 4; im++) {
            int r0 = bm + wm + im * 16 + (lane >> 2);
            #pragma unroll
            for (int in = 0; in < 4; in++) {
                int c0 = bn + wn + in * 8 + (lane & 3) * 2;
                *(float2*)(Cg + (size_t)r0 * ldc + c0) =
                    make_float2(acc[im][in][0], acc[im][in][1]);
                *(float2*)(Cg + (size_t)(r0 + 8) * ldc + c0) =
                    make_float2(acc[im][in][2], acc[im][in][3]);
            }
        }
    }
}

// ---------------- merge per-row partials -> rank row value ----------------
__global__ void k_rank() {
    int gw = (blockIdx.x * blockDim.x + threadIdx.x) >> 5;
    int lane = threadIdx.x & 31;
    if (gw >= BB) return;
    const float* pm = g_pm + (size_t)gw * 128;
    const float* ps = g_ps + (size_t)gw * 128;
    float M = -1e30f, S = 0.f;
    #pragma unroll
    for (int i = 0; i < 4; i++) {
        float m2 = pm[lane + i * 32], s2 = ps[lane + i * 32];
        float Mn = fmaxf(M, m2);
        S = S * expf(M - Mn) + s2 * expf(m2 - Mn);
        M = Mn;
    }
    #pragma unroll
    for (int o = 16; o; o >>= 1) {
        float m2 = __shfl_xor_sync(0xffffffffu, M, o);
        float s2 = __shfl_xor_sync(0xffffffffu, S, o);
        float Mn = fmaxf(M, m2);
        S = S * expf(M - Mn) + s2 * expf(m2 - Mn);
        M = Mn;
    }
    if (lane == 0) g_rowv[gw] = M + logf(S) - g_lablogit[gw];
}

// ---------------- per-row KD KL ----------------
__global__ void k_kd() {
    int b = blockIdx.x, t = threadIdx.x;
    int labb = g_lab32[b];
    const float* sr = g_sim  + (size_t)b * BB;
    const float* tr = g_tsim + (size_t)b * BB;
    float Mx = -1e30f, Sx = 0.f, My = -1e30f, Sy = 0.f, U = 0.f;
    for (int j = t; j < BB; j += 256) {
        float sc = (g_lab32[j] == labb) ? 0.25f : 0.125f;  // scale/TAU
        float x = sr[j] * sc, y = tr[j] * sc;
        if (x <= Mx) Sx += expf(x - Mx);
        else { Sx = Sx * expf(Mx - x) + 1.f; Mx = x; }
        float d = y - x;
        if (y <= My) { float e = expf(y - My); Sy += e; U += e * d; }
        else { float r = expf(My - y); Sy = Sy * r + 1.f; U = U * r + d; My = y; }
    }
    __shared__ float sMx[256], sSx[256], sMy[256], sSy[256], sU[256];
    sMx[t] = Mx; sSx[t] = Sx; sMy[t] = My; sSy[t] = Sy; sU[t] = U;
    __syncthreads();
    for (int s = 128; s > 0; s >>= 1) {
        if (t < s) {
            float m2 = sMx[t + s], s2 = sSx[t + s];
            float Mn = fmaxf(sMx[t], m2);
            sSx[t] = sSx[t] * expf(sMx[t] - Mn) + s2 * expf(m2 - Mn);
            sMx[t] = Mn;
            float my2 = sMy[t + s], sy2 = sSy[t + s], u2 = sU[t + s];
            float Myn = fmaxf(sMy[t], my2);
            float r1 = expf(sMy[t] - Myn), r2 = expf(my2 - Myn);
            sSy[t] = sSy[t] * r1 + sy2 * r2;
            sU[t]  = sU[t]  * r1 + u2  * r2;
            sMy[t] = Myn;
        }
        __syncthreads();
    }
    if (t == 0) {
        float lsex = sMx[0] + logf(sSx[0]);
        float lsey = sMy[0] + logf(sSy[0]);
        g_kl[b] = sU[0] / sSy[0] + lsex - lsey;
    }
}

// ---------------- final deterministic reduction ----------------
__global__ void k_final(const int* __restrict__ epoch_raw, int have_epoch,
                        float* __restrict__ out, int out_size) {
    int t = threadIdx.x;
    float a = 0.f, b = 0.f;
    for (int i = t; i < BB; i += 256) { a += g_rowv[i]; b += g_kl[i]; }
    __shared__ float sa[256], sb[256];
    sa[t] = a; sb[t] = b;
    __syncthreads();
    for (int s = 128; s > 0; s >>= 1) {
        if (t < s) { sa[t] += sa[t + s]; sb[t] += sb[t + s]; }
        __syncthreads();
    }
    if (t == 0) {
        float ep = 75.0f;
        if (have_epoch) {
            int iv = epoch_raw[0];
            if (iv >= 0 && iv <= 1000000) ep = (float)iv;
            else ep = __int_as_float(iv);
        }
        float loss_rank = sa[0] * (1.0f / BB);
        float loss_kd   = sb[0] * (1.0f / BB);
        float ramp = (ep / 150.0f) * 16.0f;
        float loss = loss_rank + ramp * loss_kd;
        out[0] = loss;
        if (out_size > 1) out[1] = loss_rank;
        if (out_size > 2) out[2] = loss_kd;
    }
}

// ---------------- launch ----------------
extern "C" void kernel_launch(void* const* d_in, const int* in_sizes, int n_in,
                              void* d_out, int out_size) {
    const float* batch   = (const float*)d_in[0];
    const float* teacher = (const float*)d_in[1];
    const float* cmap    = (const float*)d_in[2];
    const int*   labraw  = (const int*)d_in[3];
    const int*   epochp  = (n_in >= 5) ? (const int*)d_in[4] : (const int*)d_in[3];
    int have_epoch = (n_in >= 5) ? 1 : 0;
    float* out = (float*)d_out;

    k_labels<<<1, 256>>>(labraw);
    k_prep_cm<<<CC, 128>>>(cmap);
    k_prep_vec<<<512, 256>>>(batch, teacher);
    k_lab<<<BB / 8, 256>>>(batch, cmap);

    dim3 gL(BB / 128, CC / 128);                    // 16 x 128
    k_gemm<0><<<gL, 256>>>();
    dim3 gS(BB / 128, BB / 128);                    // 16 x 16
    k_gemm<1><<<gS, 256>>>();
    k_gemm<2><<<gS, 256>>>();

    k_rank<<<BB / 8, 256>>>();
    k_kd<<<BB, 256>>>();
    k_final<<<1, 256>>>(epochp, have_epoch, out, out_size);
}